// round 2
// baseline (speedup 1.0000x reference)
#include <cuda_runtime.h>
#include <cstdint>

#define NN 100000
#define NE_MAX 3300000
#define F_IN 512
#define HIDDEN 16
#define NCLS 10

// ---------------- scratch (no allocation allowed) ----------------
__device__ int   g_degi[NN];
__device__ float g_dinv[NN];
__device__ int   g_off[NN + 1];
__device__ int   g_cursor[NN];
__device__ int   g_csr[NE_MAX];                // src node per CSR slot (grouped by dst)
__device__ float g_h1s[(size_t)NN * HIDDEN];   // dinv[src]-prescaled layer-1 features
__device__ float g_h2s[(size_t)NN * NCLS];     // dinv[src]-prescaled layer-2 features
__device__ int   g_is64;

#define FULL 0xffffffffu

// ---------------- edge-index dtype detection ----------------
// int64 with ids < 2^17 -> every odd 32-bit word of the first 32 values is 0.
__global__ void detect_k(const int* __restrict__ ei) {
    int all0 = 1;
    #pragma unroll
    for (int k = 0; k < 32; k++) if (ei[2 * k + 1] != 0) all0 = 0;
    g_is64 = all0;
}

__device__ __forceinline__ void load_edge(const void* ei, long long e, long long E,
                                          int is64, int& src, int& dst) {
    if (is64) {
        const long long* p = (const long long*)ei;
        src = (int)p[e]; dst = (int)p[E + e];
    } else {
        const int* p = (const int*)ei;
        src = p[e]; dst = p[E + e];
    }
}

// ---------------- degree (int) ----------------
__global__ void zero_k(int n) {
    int i = blockIdx.x * blockDim.x + threadIdx.x;
    if (i < n) g_degi[i] = 0;
}

__global__ void deg_k(const void* __restrict__ ei, long long E) {
    long long e = (long long)blockIdx.x * blockDim.x + threadIdx.x;
    if (e >= E) return;
    int dst;
    if (g_is64) dst = (int)((const long long*)ei)[E + e];
    else        dst = ((const int*)ei)[E + e];
    atomicAdd(&g_degi[dst], 1);
}

// ---------------- single-block scan: offsets, cursors, dinv ----------------
#define SCAN_T 1024
__global__ __launch_bounds__(SCAN_T) void scan_k(int n, int Etot) {
    const int C = (NN + SCAN_T - 1) / SCAN_T;   // 98
    int t = threadIdx.x, lane = t & 31, wid = t >> 5;
    int lo = t * C, hi = min(lo + C, n);
    int s = 0;
    for (int i = lo; i < hi; i++) s += g_degi[i];
    // inclusive warp scan
    int v = s;
    #pragma unroll
    for (int d = 1; d < 32; d <<= 1) {
        int u = __shfl_up_sync(FULL, v, d);
        if (lane >= d) v += u;
    }
    __shared__ int wsum[32];
    if (lane == 31) wsum[wid] = v;
    __syncthreads();
    if (wid == 0) {
        int w = wsum[lane];
        int wv = w;
        #pragma unroll
        for (int d = 1; d < 32; d <<= 1) {
            int u = __shfl_up_sync(FULL, wv, d);
            if (lane >= d) wv += u;
        }
        wsum[lane] = wv - w;   // exclusive warp offset
    }
    __syncthreads();
    int pre = wsum[wid] + (v - s);  // exclusive prefix for this thread
    for (int i = lo; i < hi; i++) {
        int d = g_degi[i];
        g_off[i] = pre;
        g_cursor[i] = pre;
        g_dinv[i] = rsqrtf((float)d + 1.0f);   // +1 self-loop
        pre += d;
    }
    if (t == 0) g_off[n] = Etot;
}

// ---------------- CSR build (counting-sort scatter, int atomics) ----------------
__global__ void csr_k(const void* __restrict__ ei, long long E) {
    long long e = (long long)blockIdx.x * blockDim.x + threadIdx.x;
    if (e >= E) return;
    int src, dst;
    load_edge(ei, e, E, g_is64, src, dst);
    int slot = atomicAdd(&g_cursor[dst], 1);
    g_csr[slot] = src;
}

// ---------------- GEMM1: h1s = (x @ W1) * dinv ----------------
#define G1_BLK 128
#define G1_KC 16
__global__ __launch_bounds__(G1_BLK) void gemm1_k(const float* __restrict__ x,
                                                  const float* __restrict__ W1, int n) {
    __shared__ float Ws[F_IN * HIDDEN];    // 32 KB
    __shared__ float xs[G1_BLK][G1_KC + 1];
    for (int i = threadIdx.x; i < F_IN * HIDDEN; i += G1_BLK) Ws[i] = W1[i];

    int base = blockIdx.x * G1_BLK;
    int node = base + threadIdx.x;
    float acc[HIDDEN];
    #pragma unroll
    for (int j = 0; j < HIDDEN; j++) acc[j] = 0.0f;

    for (int kc = 0; kc < F_IN; kc += G1_KC) {
        __syncthreads();
        #pragma unroll
        for (int i = 0; i < G1_KC; i++) {
            int idx = threadIdx.x + i * G1_BLK;
            int r = idx >> 4, c = idx & 15;
            int nn = base + r;
            xs[r][c] = (nn < n) ? x[(size_t)nn * F_IN + kc + c] : 0.0f;
        }
        __syncthreads();
        #pragma unroll
        for (int c = 0; c < G1_KC; c++) {
            float xv = xs[threadIdx.x][c];
            const float4* w = (const float4*)&Ws[(kc + c) * HIDDEN];
            float4 w0 = w[0], w1 = w[1], w2 = w[2], w3 = w[3];
            acc[0]  = fmaf(xv, w0.x, acc[0]);  acc[1]  = fmaf(xv, w0.y, acc[1]);
            acc[2]  = fmaf(xv, w0.z, acc[2]);  acc[3]  = fmaf(xv, w0.w, acc[3]);
            acc[4]  = fmaf(xv, w1.x, acc[4]);  acc[5]  = fmaf(xv, w1.y, acc[5]);
            acc[6]  = fmaf(xv, w1.z, acc[6]);  acc[7]  = fmaf(xv, w1.w, acc[7]);
            acc[8]  = fmaf(xv, w2.x, acc[8]);  acc[9]  = fmaf(xv, w2.y, acc[9]);
            acc[10] = fmaf(xv, w2.z, acc[10]); acc[11] = fmaf(xv, w2.w, acc[11]);
            acc[12] = fmaf(xv, w3.x, acc[12]); acc[13] = fmaf(xv, w3.y, acc[13]);
            acc[14] = fmaf(xv, w3.z, acc[14]); acc[15] = fmaf(xv, w3.w, acc[15]);
        }
    }
    if (node < n) {
        float di = g_dinv[node];
        float4* h = (float4*)(g_h1s + (size_t)node * HIDDEN);
        #pragma unroll
        for (int q = 0; q < 4; q++)
            h[q] = make_float4(acc[4 * q + 0] * di, acc[4 * q + 1] * di,
                               acc[4 * q + 2] * di, acc[4 * q + 3] * di);
    }
}

// ---------------- agg1 fused: gather-sum h1s + self, *dinv, +b1, relu, @W2, *dinv -> h2s ----
#define AGG_BLK 256
__global__ __launch_bounds__(AGG_BLK) void agg1_k(const float* __restrict__ b1,
                                                  const float* __restrict__ W2, int n) {
    __shared__ float W2s[HIDDEN * NCLS];
    __shared__ float b1s[HIDDEN];
    if (threadIdx.x < HIDDEN * NCLS) W2s[threadIdx.x] = W2[threadIdx.x];
    if (threadIdx.x < HIDDEN) b1s[threadIdx.x] = b1[threadIdx.x];
    __syncthreads();

    int wid = threadIdx.x >> 5, lane = threadIdx.x & 31;
    int v = blockIdx.x * (AGG_BLK / 32) + wid;
    if (v >= n) return;

    int start = g_off[v], end = g_off[v + 1];
    int half = lane >> 4, f = lane & 15;
    float acc0 = 0.f, acc1 = 0.f;

    for (int chunk = start; chunk < end; chunk += 32) {
        int m = min(32, end - chunk);
        int srcs = (lane < m) ? g_csr[chunk + lane] : 0;
        for (int k = 0; k < m; k += 4) {           // uniform across warp
            int jA = k + half;                     // covers j mod 4 in {0,1}
            int jB = k + 2 + half;                 // covers j mod 4 in {2,3}
            int sA = __shfl_sync(FULL, srcs, jA & 31);
            int sB = __shfl_sync(FULL, srcs, jB & 31);
            if (jA < m) acc0 += g_h1s[(size_t)sA * HIDDEN + f];
            if (jB < m) acc1 += g_h1s[(size_t)sB * HIDDEN + f];
        }
    }
    float acc = acc0 + acc1;
    acc += __shfl_xor_sync(FULL, acc, 16);         // combine halves; all lanes hold sum(f)
    float di = g_dinv[v];
    acc += g_h1s[(size_t)v * HIDDEN + f];          // self loop (already *dinv[v])
    float hr = fmaxf(fmaf(acc, di, b1s[f]), 0.0f); // lane holds hrelu[f], f = lane&15

    // in-warp GEMM2: out[c] = sum_j hrelu[j] * W2[j][c], lanes 0..9 produce c=lane
    int c = (lane < NCLS) ? lane : 0;
    float o = 0.f;
    #pragma unroll
    for (int j = 0; j < HIDDEN; j++) {
        float hj = __shfl_sync(FULL, hr, j);       // lane j holds hrelu[j]
        o = fmaf(hj, W2s[j * NCLS + c], o);
    }
    if (lane < NCLS) g_h2s[(size_t)v * NCLS + lane] = o * di;
}

// ---------------- agg2: gather-sum h2s + self, *dinv, +b2 -> out ----------------
__global__ __launch_bounds__(AGG_BLK) void agg2_k(const float* __restrict__ b2,
                                                  float* __restrict__ out, int n) {
    int wid = threadIdx.x >> 5, lane = threadIdx.x & 31;
    int v = blockIdx.x * (AGG_BLK / 32) + wid;
    if (v >= n) return;

    int start = g_off[v], end = g_off[v + 1];
    bool active = lane < 30;
    int g = active ? lane / NCLS : 0;              // group 0..2
    int f = active ? (lane - g * NCLS) : 0;        // feature 0..9
    float acc0 = 0.f, acc1 = 0.f;

    for (int chunk = start; chunk < end; chunk += 30) {
        int m = min(30, end - chunk);
        int srcs = (lane < m) ? g_csr[chunk + lane] : 0;
        for (int k = 0; k < m; k += 6) {           // uniform across warp
            int jA = k + g;                        // j mod 6 in {0,1,2}
            int jB = k + 3 + g;                    // j mod 6 in {3,4,5}
            int sA = __shfl_sync(FULL, srcs, jA & 31);
            int sB = __shfl_sync(FULL, srcs, jB & 31);
            if (active && jA < m) acc0 += g_h2s[(size_t)sA * NCLS + f];
            if (active && jB < m) acc1 += g_h2s[(size_t)sB * NCLS + f];
        }
    }
    float t = acc0 + acc1;
    float u1 = __shfl_down_sync(FULL, t, 10);
    float u2 = __shfl_down_sync(FULL, t, 20);
    if (lane < NCLS) {
        float total = t + u1 + u2 + g_h2s[(size_t)v * NCLS + lane];  // + self
        out[(size_t)v * NCLS + lane] = fmaf(total, g_dinv[v], b2[lane]);
    }
}

// ---------------- launch ----------------
extern "C" void kernel_launch(void* const* d_in, const int* in_sizes, int n_in,
                              void* d_out, int out_size) {
    const float* x  = (const float*)d_in[0];
    const void*  ei = d_in[1];
    const float* W1 = (const float*)d_in[2];
    const float* b1 = (const float*)d_in[3];
    const float* W2 = (const float*)d_in[4];
    const float* b2 = (const float*)d_in[5];
    float* out = (float*)d_out;

    int n = in_sizes[0] / F_IN;                 // 100000
    long long E = (long long)in_sizes[1] / 2;   // 3200000

    int nb_n  = (n + 255) / 256;
    int nb_e  = (int)((E + 255) / 256);
    int nb_g1 = (n + G1_BLK - 1) / G1_BLK;
    int nb_ag = (n + (AGG_BLK / 32) - 1) / (AGG_BLK / 32);

    detect_k<<<1, 1>>>((const int*)ei);
    zero_k<<<nb_n, 256>>>(n);
    deg_k<<<nb_e, 256>>>(ei, E);
    scan_k<<<1, SCAN_T>>>(n, (int)E);
    csr_k<<<nb_e, 256>>>(ei, E);
    gemm1_k<<<nb_g1, G1_BLK>>>(x, W1, n);
    agg1_k<<<nb_ag, AGG_BLK>>>(b1, W2, n);
    agg2_k<<<nb_ag, AGG_BLK>>>(b2, out, n);
}

// round 3
// speedup vs baseline: 1.7779x; 1.7779x over previous
#include <cuda_runtime.h>
#include <cstdint>

#define NN 100000
#define NE_MAX 3300000
#define F_IN 512
#define HIDDEN 16
#define NCLS 10
#define H2_PAD 16
#define SB 256
#define NB_SCAN ((NN + SB - 1) / SB)   // 391

// ---------------- scratch (no allocation allowed) ----------------
__device__ int   g_degi[NN];
__device__ float g_dinv[NN];
__device__ int   g_off[NN + 1];
__device__ int   g_cursor[NN];
__device__ int   g_csr[NE_MAX];                 // src node per CSR slot (grouped by dst)
__device__ float g_h1s[(size_t)NN * HIDDEN];    // dinv[src]-prescaled layer-1 features
__device__ float g_h2s[(size_t)NN * H2_PAD];    // dinv[src]-prescaled layer-2 (padded w/ 0)
__device__ int   g_bsum[NB_SCAN];
__device__ int   g_boff[NB_SCAN];
__device__ int   g_is64;

#define FULL 0xffffffffu

// ---------------- edge-index dtype detection ----------------
__global__ void detect_k(const int* __restrict__ ei) {
    int all0 = 1;
    #pragma unroll
    for (int k = 0; k < 32; k++) if (ei[2 * k + 1] != 0) all0 = 0;
    g_is64 = all0;
}

__device__ __forceinline__ void load_edge(const void* ei, long long e, long long E,
                                          int is64, int& src, int& dst) {
    if (is64) {
        const long long* p = (const long long*)ei;
        src = (int)p[e]; dst = (int)p[E + e];
    } else {
        const int* p = (const int*)ei;
        src = p[e]; dst = p[E + e];
    }
}

// ---------------- degree ----------------
__global__ void zero_k(int n) {
    int i = blockIdx.x * blockDim.x + threadIdx.x;
    if (i < n) g_degi[i] = 0;
}

__global__ void deg_k(const void* __restrict__ ei, long long E) {
    long long e = (long long)blockIdx.x * blockDim.x + threadIdx.x;
    if (e >= E) return;
    int dst;
    if (g_is64) dst = (int)((const long long*)ei)[E + e];
    else        dst = ((const int*)ei)[E + e];
    atomicAdd(&g_degi[dst], 1);
}

// ---------------- hierarchical exclusive scan of degrees ----------------
__global__ __launch_bounds__(SB) void blocksum_k(int n) {
    __shared__ int sh[SB / 32];
    int i = blockIdx.x * SB + threadIdx.x;
    int lane = threadIdx.x & 31, wid = threadIdx.x >> 5;
    int v = (i < n) ? g_degi[i] : 0;
    #pragma unroll
    for (int d = 16; d; d >>= 1) v += __shfl_down_sync(FULL, v, d);
    if (lane == 0) sh[wid] = v;
    __syncthreads();
    if (threadIdx.x == 0) {
        int s = 0;
        #pragma unroll
        for (int w = 0; w < SB / 32; w++) s += sh[w];
        g_bsum[blockIdx.x] = s;
    }
}

__global__ __launch_bounds__(512) void bscan_k(int nb) {
    __shared__ int sh[512];
    int t = threadIdx.x;
    int v = (t < nb) ? g_bsum[t] : 0;
    sh[t] = v;
    __syncthreads();
    #pragma unroll
    for (int d = 1; d < 512; d <<= 1) {
        int u = (t >= d) ? sh[t - d] : 0;
        __syncthreads();
        sh[t] += u;
        __syncthreads();
    }
    if (t < nb) g_boff[t] = sh[t] - v;   // exclusive
}

__global__ __launch_bounds__(SB) void fill_k(int n, int Etot) {
    __shared__ int ws[SB / 32];
    int i = blockIdx.x * SB + threadIdx.x;
    int lane = threadIdx.x & 31, wid = threadIdx.x >> 5;
    int d = (i < n) ? g_degi[i] : 0;
    int v = d;
    #pragma unroll
    for (int s = 1; s < 32; s <<= 1) {
        int u = __shfl_up_sync(FULL, v, s);
        if (lane >= s) v += u;
    }
    if (lane == 31) ws[wid] = v;
    __syncthreads();
    if (threadIdx.x == 0) {
        int s = 0;
        #pragma unroll
        for (int w = 0; w < SB / 32; w++) { int t = ws[w]; ws[w] = s; s += t; }
    }
    __syncthreads();
    int ex = g_boff[blockIdx.x] + ws[wid] + (v - d);
    if (i < n) {
        g_off[i] = ex;
        g_cursor[i] = ex;
        g_dinv[i] = rsqrtf((float)d + 1.0f);
    }
    if (blockIdx.x == 0 && threadIdx.x == 0) g_off[n] = Etot;
}

// ---------------- CSR build ----------------
__global__ void csr_k(const void* __restrict__ ei, long long E) {
    long long e = (long long)blockIdx.x * blockDim.x + threadIdx.x;
    if (e >= E) return;
    int src, dst;
    load_edge(ei, e, E, g_is64, src, dst);
    int slot = atomicAdd(&g_cursor[dst], 1);
    g_csr[slot] = src;
}

// ---------------- GEMM1: h1s = (x @ W1) * dinv ----------------
#define G1_BLK 128
#define G1_KC 16
__global__ __launch_bounds__(G1_BLK) void gemm1_k(const float* __restrict__ x,
                                                  const float* __restrict__ W1, int n) {
    __shared__ float Ws[F_IN * HIDDEN];
    __shared__ float xs[G1_BLK][G1_KC + 1];
    for (int i = threadIdx.x; i < F_IN * HIDDEN; i += G1_BLK) Ws[i] = W1[i];

    int base = blockIdx.x * G1_BLK;
    int node = base + threadIdx.x;
    float acc[HIDDEN];
    #pragma unroll
    for (int j = 0; j < HIDDEN; j++) acc[j] = 0.0f;

    for (int kc = 0; kc < F_IN; kc += G1_KC) {
        __syncthreads();
        #pragma unroll
        for (int i = 0; i < G1_KC; i++) {
            int idx = threadIdx.x + i * G1_BLK;
            int r = idx >> 4, c = idx & 15;
            int nn = base + r;
            xs[r][c] = (nn < n) ? x[(size_t)nn * F_IN + kc + c] : 0.0f;
        }
        __syncthreads();
        #pragma unroll
        for (int c = 0; c < G1_KC; c++) {
            float xv = xs[threadIdx.x][c];
            const float4* w = (const float4*)&Ws[(kc + c) * HIDDEN];
            float4 w0 = w[0], w1 = w[1], w2 = w[2], w3 = w[3];
            acc[0]  = fmaf(xv, w0.x, acc[0]);  acc[1]  = fmaf(xv, w0.y, acc[1]);
            acc[2]  = fmaf(xv, w0.z, acc[2]);  acc[3]  = fmaf(xv, w0.w, acc[3]);
            acc[4]  = fmaf(xv, w1.x, acc[4]);  acc[5]  = fmaf(xv, w1.y, acc[5]);
            acc[6]  = fmaf(xv, w1.z, acc[6]);  acc[7]  = fmaf(xv, w1.w, acc[7]);
            acc[8]  = fmaf(xv, w2.x, acc[8]);  acc[9]  = fmaf(xv, w2.y, acc[9]);
            acc[10] = fmaf(xv, w2.z, acc[10]); acc[11] = fmaf(xv, w2.w, acc[11]);
            acc[12] = fmaf(xv, w3.x, acc[12]); acc[13] = fmaf(xv, w3.y, acc[13]);
            acc[14] = fmaf(xv, w3.z, acc[14]); acc[15] = fmaf(xv, w3.w, acc[15]);
        }
    }
    if (node < n) {
        float di = g_dinv[node];
        float4* h = (float4*)(g_h1s + (size_t)node * HIDDEN);
        #pragma unroll
        for (int q = 0; q < 4; q++)
            h[q] = make_float4(acc[4 * q + 0] * di, acc[4 * q + 1] * di,
                               acc[4 * q + 2] * di, acc[4 * q + 3] * di);
    }
}

// ---------------- float4 warp gather over CSR ----------------
// Each lane loads float4 component c4 = lane&3 of row g = lane>>2 (8 rows per
// iteration). After xor-reduction (4,8,16) every lane holds the column-block
// sum for its own c4. Lane L (< 16) then extracts component (L>>2), i.e. lane L
// holds feature f(L) = 4*(L&3) + (L>>2).
__device__ __forceinline__ float4 csr_gather16(const float* __restrict__ tab,
                                               int row_stride, int start, int end,
                                               int lane) {
    int c4 = lane & 3;
    int g = lane >> 2;
    float4 acc = make_float4(0.f, 0.f, 0.f, 0.f);
    for (int chunk = start; chunk < end; chunk += 32) {
        int m = min(32, end - chunk);
        int srcs = (lane < m) ? g_csr[chunk + lane] : 0;
        #pragma unroll 4
        for (int k = 0; k < m; k += 8) {
            int j = k + g;
            int s = __shfl_sync(FULL, srcs, j & 31);
            if (j < m) {
                float4 t = ((const float4*)(tab + (size_t)s * row_stride))[c4];
                acc.x += t.x; acc.y += t.y; acc.z += t.z; acc.w += t.w;
            }
        }
    }
    #pragma unroll
    for (int d = 4; d < 32; d <<= 1) {
        acc.x += __shfl_xor_sync(FULL, acc.x, d);
        acc.y += __shfl_xor_sync(FULL, acc.y, d);
        acc.z += __shfl_xor_sync(FULL, acc.z, d);
        acc.w += __shfl_xor_sync(FULL, acc.w, d);
    }
    return acc;
}

__device__ __forceinline__ float pick(float4 v, int comp) {
    float r = v.x;
    if (comp == 1) r = v.y;
    if (comp == 2) r = v.z;
    if (comp == 3) r = v.w;
    return r;
}

// lane holding feature j: L(j) = (j>>2) + 4*(j&3)
#define LANE_OF(j) (((j) >> 2) + 4 * ((j) & 3))

// ---------------- agg1 fused: gather + self, *dinv, +b1, relu, @W2, *dinv -> h2s ----
#define AGG_BLK 256
__global__ __launch_bounds__(AGG_BLK) void agg1_k(const float* __restrict__ b1,
                                                  const float* __restrict__ W2, int n) {
    __shared__ float W2s[HIDDEN * NCLS];
    __shared__ float b1s[HIDDEN];
    if (threadIdx.x < HIDDEN * NCLS) W2s[threadIdx.x] = W2[threadIdx.x];
    if (threadIdx.x < HIDDEN) b1s[threadIdx.x] = b1[threadIdx.x];
    __syncthreads();

    int wid = threadIdx.x >> 5, lane = threadIdx.x & 31;
    int v = blockIdx.x * (AGG_BLK / 32) + wid;
    if (v >= n) return;

    float4 acc4 = csr_gather16(g_h1s, HIDDEN, g_off[v], g_off[v + 1], lane);

    int f = (4 * (lane & 3) + ((lane >> 2) & 3)) & 15;   // feature owned by this lane
    float acc = pick(acc4, (lane >> 2) & 3);
    float di = g_dinv[v];
    acc += g_h1s[(size_t)v * HIDDEN + f];                // self loop (prescaled)
    float hr = fmaxf(fmaf(acc, di, b1s[f]), 0.0f);       // valid on lanes 0..15

    // in-warp GEMM2: o[c] = sum_j hrelu[j] * W2[j][c]
    int c = (lane < NCLS) ? lane : 0;
    float o = 0.f;
    #pragma unroll
    for (int j = 0; j < HIDDEN; j++) {
        float hj = __shfl_sync(FULL, hr, LANE_OF(j));
        o = fmaf(hj, W2s[j * NCLS + c], o);
    }
    if (lane < HIDDEN)
        g_h2s[(size_t)v * H2_PAD + lane] = (lane < NCLS) ? o * di : 0.0f;
}

// ---------------- agg2: gather + self, *dinv, +b2 -> out ----------------
__global__ __launch_bounds__(AGG_BLK) void agg2_k(const float* __restrict__ b2,
                                                  float* __restrict__ out, int n) {
    int wid = threadIdx.x >> 5, lane = threadIdx.x & 31;
    int v = blockIdx.x * (AGG_BLK / 32) + wid;
    if (v >= n) return;

    float4 acc4 = csr_gather16(g_h2s, H2_PAD, g_off[v], g_off[v + 1], lane);

    int f = (4 * (lane & 3) + ((lane >> 2) & 3)) & 15;
    float acc = pick(acc4, (lane >> 2) & 3);
    if (lane < 16 && f < NCLS) {
        float total = acc + g_h2s[(size_t)v * H2_PAD + f];   // + self
        out[(size_t)v * NCLS + f] = fmaf(total, g_dinv[v], b2[f]);
    }
}

// ---------------- launch ----------------
extern "C" void kernel_launch(void* const* d_in, const int* in_sizes, int n_in,
                              void* d_out, int out_size) {
    const float* x  = (const float*)d_in[0];
    const void*  ei = d_in[1];
    const float* W1 = (const float*)d_in[2];
    const float* b1 = (const float*)d_in[3];
    const float* W2 = (const float*)d_in[4];
    const float* b2 = (const float*)d_in[5];
    float* out = (float*)d_out;

    int n = in_sizes[0] / F_IN;                 // 100000
    long long E = (long long)in_sizes[1] / 2;   // 3200000

    int nb_n  = (n + 255) / 256;
    int nb_e  = (int)((E + 255) / 256);
    int nb_g1 = (n + G1_BLK - 1) / G1_BLK;
    int nb_sc = (n + SB - 1) / SB;
    int nb_ag = (n + (AGG_BLK / 32) - 1) / (AGG_BLK / 32);

    detect_k<<<1, 1>>>((const int*)ei);
    zero_k<<<nb_n, 256>>>(n);
    deg_k<<<nb_e, 256>>>(ei, E);
    blocksum_k<<<nb_sc, SB>>>(n);
    bscan_k<<<1, 512>>>(nb_sc);
    fill_k<<<nb_sc, SB>>>(n, (int)E);
    csr_k<<<nb_e, 256>>>(ei, E);
    gemm1_k<<<nb_g1, G1_BLK>>>(x, W1, n);
    agg1_k<<<nb_ag, AGG_BLK>>>(b1, W2, n);
    agg2_k<<<nb_ag, AGG_BLK>>>(b2, out, n);
}

// round 4
// speedup vs baseline: 1.8512x; 1.0412x over previous
#include <cuda_runtime.h>
#include <cstdint>

#define NN 100000
#define NE_MAX 3300000
#define F_IN 512
#define HIDDEN 16
#define NCLS 10
#define H2_PAD 16
#define SB 256
#define NB_SCAN ((NN + SB - 1) / SB)   // 391

// ---------------- scratch (no allocation allowed) ----------------
__device__ int   g_degi[NN];
__device__ float g_dinv[NN];
__device__ int   g_off[NN + 1];
__device__ int   g_cursor[NN];
__device__ int   g_csr[NE_MAX];
__device__ __align__(16) float g_h1s[(size_t)NN * HIDDEN];
__device__ __align__(16) float g_h2s[(size_t)NN * H2_PAD];
__device__ int   g_bsum[NB_SCAN];
__device__ int   g_boff[NB_SCAN];
__device__ int   g_is64;

#define FULL 0xffffffffu

__device__ __forceinline__ void load_edge(const void* ei, long long e, long long E,
                                          int is64, int& src, int& dst) {
    if (is64) {
        const long long* p = (const long long*)ei;
        src = (int)p[e]; dst = (int)p[E + e];
    } else {
        const int* p = (const int*)ei;
        src = p[e]; dst = p[E + e];
    }
}

// ---------------- zero degrees + edge-dtype detect (fused) ----------------
__global__ void zero_k(const int* __restrict__ ei, int n) {
    int i = blockIdx.x * blockDim.x + threadIdx.x;
    if (i < n) g_degi[i] = 0;
    if (i == 0) {
        // int64 with ids < 2^17 -> every odd 32-bit word of first 32 values is 0
        int all0 = 1;
        #pragma unroll
        for (int k = 0; k < 32; k++) if (ei[2 * k + 1] != 0) all0 = 0;
        g_is64 = all0;
    }
}

__global__ void deg_k(const void* __restrict__ ei, long long E) {
    long long e = (long long)blockIdx.x * blockDim.x + threadIdx.x;
    if (e >= E) return;
    int dst;
    if (g_is64) dst = (int)((const long long*)ei)[E + e];
    else        dst = ((const int*)ei)[E + e];
    atomicAdd(&g_degi[dst], 1);
}

// ---------------- hierarchical exclusive scan of degrees ----------------
__global__ __launch_bounds__(SB) void blocksum_k(int n) {
    __shared__ int sh[SB / 32];
    int i = blockIdx.x * SB + threadIdx.x;
    int lane = threadIdx.x & 31, wid = threadIdx.x >> 5;
    int v = (i < n) ? g_degi[i] : 0;
    #pragma unroll
    for (int d = 16; d; d >>= 1) v += __shfl_down_sync(FULL, v, d);
    if (lane == 0) sh[wid] = v;
    __syncthreads();
    if (threadIdx.x == 0) {
        int s = 0;
        #pragma unroll
        for (int w = 0; w < SB / 32; w++) s += sh[w];
        g_bsum[blockIdx.x] = s;
    }
}

__global__ __launch_bounds__(512) void bscan_k(int nb) {
    __shared__ int sh[512];
    int t = threadIdx.x;
    int v = (t < nb) ? g_bsum[t] : 0;
    sh[t] = v;
    __syncthreads();
    #pragma unroll
    for (int d = 1; d < 512; d <<= 1) {
        int u = (t >= d) ? sh[t - d] : 0;
        __syncthreads();
        sh[t] += u;
        __syncthreads();
    }
    if (t < nb) g_boff[t] = sh[t] - v;   // exclusive
}

__global__ __launch_bounds__(SB) void fill_k(int n, int Etot) {
    __shared__ int ws[SB / 32];
    int i = blockIdx.x * SB + threadIdx.x;
    int lane = threadIdx.x & 31, wid = threadIdx.x >> 5;
    int d = (i < n) ? g_degi[i] : 0;
    int v = d;
    #pragma unroll
    for (int s = 1; s < 32; s <<= 1) {
        int u = __shfl_up_sync(FULL, v, s);
        if (lane >= s) v += u;
    }
    if (lane == 31) ws[wid] = v;
    __syncthreads();
    if (threadIdx.x == 0) {
        int s = 0;
        #pragma unroll
        for (int w = 0; w < SB / 32; w++) { int t = ws[w]; ws[w] = s; s += t; }
    }
    __syncthreads();
    int ex = g_boff[blockIdx.x] + ws[wid] + (v - d);
    if (i < n) {
        g_off[i] = ex;
        g_cursor[i] = ex;
        g_dinv[i] = rsqrtf((float)d + 1.0f);
    }
    if (blockIdx.x == 0 && threadIdx.x == 0) g_off[n] = Etot;
}

// ---------------- CSR build ----------------
__global__ void csr_k(const void* __restrict__ ei, long long E) {
    long long e = (long long)blockIdx.x * blockDim.x + threadIdx.x;
    if (e >= E) return;
    int src, dst;
    load_edge(ei, e, E, g_is64, src, dst);
    int slot = atomicAdd(&g_cursor[dst], 1);
    g_csr[slot] = src;
}

// ---------------- GEMM1 (FFMA2 / f32x2): h1 = x @ W1 (unscaled) ----------------
#define G1_BLK 128
#define G1_KC 16
__global__ __launch_bounds__(G1_BLK) void gemm1_k(const float* __restrict__ x,
                                                  const float* __restrict__ W1, int n) {
    __shared__ __align__(16) float Ws[F_IN * HIDDEN];   // 32 KB
    __shared__ float xs[G1_BLK][G1_KC + 1];
    for (int i = threadIdx.x; i < F_IN * HIDDEN; i += G1_BLK) Ws[i] = W1[i];

    int base = blockIdx.x * G1_BLK;
    int node = base + threadIdx.x;
    unsigned long long acc2[8];
    #pragma unroll
    for (int q = 0; q < 8; q++) acc2[q] = 0ULL;  // (0.0f, 0.0f)

    for (int kc = 0; kc < F_IN; kc += G1_KC) {
        __syncthreads();
        #pragma unroll
        for (int i = 0; i < G1_KC; i++) {
            int idx = threadIdx.x + i * G1_BLK;
            int r = idx >> 4, c = idx & 15;
            int nn = base + r;
            xs[r][c] = (nn < n) ? x[(size_t)nn * F_IN + kc + c] : 0.0f;
        }
        __syncthreads();
        #pragma unroll
        for (int c = 0; c < G1_KC; c++) {
            float xv = xs[threadIdx.x][c];
            unsigned long long xv2;
            asm("mov.b64 %0, {%1, %1};" : "=l"(xv2) : "f"(xv));
            const ulonglong2* w = (const ulonglong2*)&Ws[(kc + c) * HIDDEN];
            ulonglong2 wa = w[0];
            ulonglong2 wb = w[1];
            asm("fma.rn.f32x2 %0, %1, %2, %0;" : "+l"(acc2[0]) : "l"(xv2), "l"(wa.x));
            asm("fma.rn.f32x2 %0, %1, %2, %0;" : "+l"(acc2[1]) : "l"(xv2), "l"(wa.y));
            asm("fma.rn.f32x2 %0, %1, %2, %0;" : "+l"(acc2[2]) : "l"(xv2), "l"(wb.x));
            asm("fma.rn.f32x2 %0, %1, %2, %0;" : "+l"(acc2[3]) : "l"(xv2), "l"(wb.y));
            wa = w[2];
            wb = w[3];
            asm("fma.rn.f32x2 %0, %1, %2, %0;" : "+l"(acc2[4]) : "l"(xv2), "l"(wa.x));
            asm("fma.rn.f32x2 %0, %1, %2, %0;" : "+l"(acc2[5]) : "l"(xv2), "l"(wa.y));
            asm("fma.rn.f32x2 %0, %1, %2, %0;" : "+l"(acc2[6]) : "l"(xv2), "l"(wb.x));
            asm("fma.rn.f32x2 %0, %1, %2, %0;" : "+l"(acc2[7]) : "l"(xv2), "l"(wb.y));
        }
    }
    if (node < n) {
        float4* h = (float4*)(g_h1s + (size_t)node * HIDDEN);
        #pragma unroll
        for (int q = 0; q < 4; q++) {
            float a, b, c, d;
            asm("mov.b64 {%0, %1}, %2;" : "=f"(a), "=f"(b) : "l"(acc2[2 * q]));
            asm("mov.b64 {%0, %1}, %2;" : "=f"(c), "=f"(d) : "l"(acc2[2 * q + 1]));
            h[q] = make_float4(a, b, c, d);
        }
    }
}

// ---------------- scale1: h1s *= dinv (join point of the two streams) ----------------
__global__ void scale1_k(int n) {
    int i = blockIdx.x * blockDim.x + threadIdx.x;   // one float4 per thread
    if (i >= n * 4) return;
    float di = g_dinv[i >> 2];
    float4* p = (float4*)g_h1s + i;
    float4 v = *p;
    v.x *= di; v.y *= di; v.z *= di; v.w *= di;
    *p = v;
}

// ---------------- float4 warp gather over CSR (f32x2 adds) ----------------
// lane loads float4 component c4=lane&3 of row g=lane>>2 (8 rows/iter).
// After xor-reduce (4,8,16) lane L<16 extracts comp (L>>2): owns f = 4*(L&3)+(L>>2).
__device__ __forceinline__ float4 csr_gather16(const float* __restrict__ tab,
                                               int row_stride, int start, int end,
                                               int lane) {
    int c4 = lane & 3;
    int g = lane >> 2;
    unsigned long long a0 = 0ULL, a1 = 0ULL;
    for (int chunk = start; chunk < end; chunk += 32) {
        int m = min(32, end - chunk);
        int srcs = (lane < m) ? g_csr[chunk + lane] : 0;
        #pragma unroll 4
        for (int k = 0; k < m; k += 8) {
            int j = k + g;
            int s = __shfl_sync(FULL, srcs, j & 31);
            if (j < m) {
                ulonglong2 t = *(const ulonglong2*)(tab + (size_t)s * row_stride + c4 * 4);
                asm("add.rn.f32x2 %0, %0, %1;" : "+l"(a0) : "l"(t.x));
                asm("add.rn.f32x2 %0, %0, %1;" : "+l"(a1) : "l"(t.y));
            }
        }
    }
    float4 acc;
    asm("mov.b64 {%0, %1}, %2;" : "=f"(acc.x), "=f"(acc.y) : "l"(a0));
    asm("mov.b64 {%0, %1}, %2;" : "=f"(acc.z), "=f"(acc.w) : "l"(a1));
    #pragma unroll
    for (int d = 4; d < 32; d <<= 1) {
        acc.x += __shfl_xor_sync(FULL, acc.x, d);
        acc.y += __shfl_xor_sync(FULL, acc.y, d);
        acc.z += __shfl_xor_sync(FULL, acc.z, d);
        acc.w += __shfl_xor_sync(FULL, acc.w, d);
    }
    return acc;
}

__device__ __forceinline__ float pick(float4 v, int comp) {
    float r = v.x;
    if (comp == 1) r = v.y;
    if (comp == 2) r = v.z;
    if (comp == 3) r = v.w;
    return r;
}

#define LANE_OF(j) (((j) >> 2) + 4 * ((j) & 3))

// ---------------- agg1 fused: gather + self, *dinv, +b1, relu, @W2, *dinv -> h2s ----
#define AGG_BLK 256
__global__ __launch_bounds__(AGG_BLK) void agg1_k(const float* __restrict__ b1,
                                                  const float* __restrict__ W2, int n) {
    __shared__ float W2s[HIDDEN * NCLS];
    __shared__ float b1s[HIDDEN];
    if (threadIdx.x < HIDDEN * NCLS) W2s[threadIdx.x] = W2[threadIdx.x];
    if (threadIdx.x < HIDDEN) b1s[threadIdx.x] = b1[threadIdx.x];
    __syncthreads();

    int wid = threadIdx.x >> 5, lane = threadIdx.x & 31;
    int v = blockIdx.x * (AGG_BLK / 32) + wid;
    if (v >= n) return;

    float4 acc4 = csr_gather16(g_h1s, HIDDEN, g_off[v], g_off[v + 1], lane);

    int f = (4 * (lane & 3) + ((lane >> 2) & 3)) & 15;
    float acc = pick(acc4, (lane >> 2) & 3);
    float di = g_dinv[v];
    acc += g_h1s[(size_t)v * HIDDEN + f];                // self loop (prescaled)
    float hr = fmaxf(fmaf(acc, di, b1s[f]), 0.0f);       // valid on lanes 0..15

    int c = (lane < NCLS) ? lane : 0;
    float o = 0.f;
    #pragma unroll
    for (int j = 0; j < HIDDEN; j++) {
        float hj = __shfl_sync(FULL, hr, LANE_OF(j));
        o = fmaf(hj, W2s[j * NCLS + c], o);
    }
    if (lane < HIDDEN)
        g_h2s[(size_t)v * H2_PAD + lane] = (lane < NCLS) ? o * di : 0.0f;
}

// ---------------- agg2: gather + self, *dinv, +b2 -> out ----------------
__global__ __launch_bounds__(AGG_BLK) void agg2_k(const float* __restrict__ b2,
                                                  float* __restrict__ out, int n) {
    int wid = threadIdx.x >> 5, lane = threadIdx.x & 31;
    int v = blockIdx.x * (AGG_BLK / 32) + wid;
    if (v >= n) return;

    float4 acc4 = csr_gather16(g_h2s, H2_PAD, g_off[v], g_off[v + 1], lane);

    int f = (4 * (lane & 3) + ((lane >> 2) & 3)) & 15;
    float acc = pick(acc4, (lane >> 2) & 3);
    if (lane < 16 && f < NCLS) {
        float total = acc + g_h2s[(size_t)v * H2_PAD + f];
        out[(size_t)v * NCLS + f] = fmaf(total, g_dinv[v], b2[f]);
    }
}

// ---------------- launch (fork/join: gemm1 overlaps CSR build) ----------------
extern "C" void kernel_launch(void* const* d_in, const int* in_sizes, int n_in,
                              void* d_out, int out_size) {
    const float* x  = (const float*)d_in[0];
    const void*  ei = d_in[1];
    const float* W1 = (const float*)d_in[2];
    const float* b1 = (const float*)d_in[3];
    const float* W2 = (const float*)d_in[4];
    const float* b2 = (const float*)d_in[5];
    float* out = (float*)d_out;

    int n = in_sizes[0] / F_IN;                 // 100000
    long long E = (long long)in_sizes[1] / 2;   // 3200000

    static cudaStream_t s2 = nullptr;
    static cudaEvent_t evA = nullptr, evB = nullptr;
    if (s2 == nullptr) {   // one-time resource creation (outside capture)
        cudaStreamCreateWithFlags(&s2, cudaStreamNonBlocking);
        cudaEventCreateWithFlags(&evA, cudaEventDisableTiming);
        cudaEventCreateWithFlags(&evB, cudaEventDisableTiming);
    }

    int nb_n  = (n + 255) / 256;
    int nb_e  = (int)((E + 255) / 256);
    int nb_g1 = (n + G1_BLK - 1) / G1_BLK;
    int nb_sc = (n + SB - 1) / SB;
    int nb_ag = (n + (AGG_BLK / 32) - 1) / (AGG_BLK / 32);
    int nb_s1 = (n * 4 + 255) / 256;

    // fork: gemm1 (x, W1 only) on s2, concurrent with CSR build on default
    cudaEventRecord(evA, 0);
    cudaStreamWaitEvent(s2, evA, 0);
    gemm1_k<<<nb_g1, G1_BLK, 0, s2>>>(x, W1, n);
    cudaEventRecord(evB, s2);

    zero_k<<<nb_n, 256>>>((const int*)ei, n);
    deg_k<<<nb_e, 256>>>(ei, E);
    blocksum_k<<<nb_sc, SB>>>(n);
    bscan_k<<<1, 512>>>(nb_sc);
    fill_k<<<nb_sc, SB>>>(n, (int)E);
    csr_k<<<nb_e, 256>>>(ei, E);

    // join, then the dependent tail
    cudaStreamWaitEvent(0, evB, 0);
    scale1_k<<<nb_s1, 256>>>(n);
    agg1_k<<<nb_ag, AGG_BLK>>>(b1, W2, n);
    agg2_k<<<nb_ag, AGG_BLK>>>(b2, out, n);
}

// round 5
// speedup vs baseline: 2.1737x; 1.1742x over previous
#include <cuda_runtime.h>
#include <cstdint>

#define NN 100000
#define NE_MAX 3300000
#define F_IN 512
#define HIDDEN 16
#define NCLS 10
#define H2_PAD 16
#define SB 256
#define NB_SCAN ((NN + SB - 1) / SB)   // 391

// ---------------- scratch (no allocation allowed) ----------------
__device__ int   g_degi[NN];
__device__ float g_dinv[NN];
__device__ int   g_off[NN + 1];
__device__ int   g_cursor[NN];
__device__ int   g_csr[NE_MAX];
__device__ __align__(16) float g_h1s[(size_t)NN * HIDDEN];
__device__ __align__(16) float g_h2s[(size_t)NN * H2_PAD];
__device__ int   g_bsum[NB_SCAN];
__device__ int   g_boff[NB_SCAN];

#define FULL 0xffffffffu

// inline edge-dtype detect: int64 ids < 2^17 -> odd words zero (uniform loads)
__device__ __forceinline__ int detect_is64(const void* ei) {
    const int* w = (const int*)ei;
    return (w[1] | w[3] | w[5] | w[7]) == 0;
}

// ---------------- degree (2 edges per thread) ----------------
__global__ void deg_k(const void* __restrict__ ei, long long E) {
    long long e0 = 2LL * ((long long)blockIdx.x * blockDim.x + threadIdx.x);
    if (e0 >= E) return;
    if (detect_is64(ei)) {
        longlong2 d = ((const longlong2*)ei)[(E + e0) >> 1];
        atomicAdd(&g_degi[(int)d.x], 1);
        if (e0 + 1 < E) atomicAdd(&g_degi[(int)d.y], 1);
    } else {
        int2 d = ((const int2*)ei)[(E + e0) >> 1];
        atomicAdd(&g_degi[d.x], 1);
        if (e0 + 1 < E) atomicAdd(&g_degi[d.y], 1);
    }
}

// ---------------- hierarchical exclusive scan of degrees ----------------
__global__ __launch_bounds__(SB) void blocksum_k(int n) {
    __shared__ int sh[SB / 32];
    int i = blockIdx.x * SB + threadIdx.x;
    int lane = threadIdx.x & 31, wid = threadIdx.x >> 5;
    int v = (i < n) ? g_degi[i] : 0;
    #pragma unroll
    for (int d = 16; d; d >>= 1) v += __shfl_down_sync(FULL, v, d);
    if (lane == 0) sh[wid] = v;
    __syncthreads();
    if (threadIdx.x == 0) {
        int s = 0;
        #pragma unroll
        for (int w = 0; w < SB / 32; w++) s += sh[w];
        g_bsum[blockIdx.x] = s;
    }
}

__global__ __launch_bounds__(512) void bscan_k(int nb) {
    __shared__ int sh[512];
    int t = threadIdx.x;
    int v = (t < nb) ? g_bsum[t] : 0;
    sh[t] = v;
    __syncthreads();
    #pragma unroll
    for (int d = 1; d < 512; d <<= 1) {
        int u = (t >= d) ? sh[t - d] : 0;
        __syncthreads();
        sh[t] += u;
        __syncthreads();
    }
    if (t < nb) g_boff[t] = sh[t] - v;   // exclusive
}

__global__ __launch_bounds__(SB) void fill_k(int n, int Etot) {
    __shared__ int ws[SB / 32];
    int i = blockIdx.x * SB + threadIdx.x;
    int lane = threadIdx.x & 31, wid = threadIdx.x >> 5;
    int d = (i < n) ? g_degi[i] : 0;
    int v = d;
    #pragma unroll
    for (int s = 1; s < 32; s <<= 1) {
        int u = __shfl_up_sync(FULL, v, s);
        if (lane >= s) v += u;
    }
    if (lane == 31) ws[wid] = v;
    __syncthreads();
    if (threadIdx.x == 0) {
        int s = 0;
        #pragma unroll
        for (int w = 0; w < SB / 32; w++) { int t = ws[w]; ws[w] = s; s += t; }
    }
    __syncthreads();
    int ex = g_boff[blockIdx.x] + ws[wid] + (v - d);
    if (i < n) {
        g_off[i] = ex;
        g_cursor[i] = ex;
        g_dinv[i] = rsqrtf((float)d + 1.0f);
    }
    if (blockIdx.x == 0 && threadIdx.x == 0) g_off[n] = Etot;
}

// ---------------- CSR build (2 edges per thread) ----------------
__global__ void csr_k(const void* __restrict__ ei, long long E) {
    long long e0 = 2LL * ((long long)blockIdx.x * blockDim.x + threadIdx.x);
    if (e0 >= E) return;
    int s0, s1 = 0, d0, d1 = 0;
    int have2 = (e0 + 1 < E);
    if (detect_is64(ei)) {
        const longlong2* p = (const longlong2*)ei;
        longlong2 s = p[e0 >> 1];
        longlong2 d = p[(E + e0) >> 1];
        s0 = (int)s.x; s1 = (int)s.y; d0 = (int)d.x; d1 = (int)d.y;
    } else {
        const int2* p = (const int2*)ei;
        int2 s = p[e0 >> 1];
        int2 d = p[(E + e0) >> 1];
        s0 = s.x; s1 = s.y; d0 = d.x; d1 = d.y;
    }
    int slot0 = atomicAdd(&g_cursor[d0], 1);
    g_csr[slot0] = s0;
    if (have2) {
        int slot1 = atomicAdd(&g_cursor[d1], 1);
        g_csr[slot1] = s1;
    }
}

// ---------------- GEMM1 (FFMA2, double-buffered, float4 loads) ----------------
#define G1_BLK 128
#define G1_KC 16
#define G1_NCH (F_IN / G1_KC)   // 32
__global__ __launch_bounds__(G1_BLK) void gemm1_k(const float* __restrict__ x,
                                                  const float* __restrict__ W1, int n) {
    __shared__ __align__(16) float Ws[F_IN * HIDDEN];       // 32 KB
    __shared__ float xs[2][G1_BLK][G1_KC + 1];               // 2 x 8.5 KB
    for (int i = threadIdx.x; i < F_IN * HIDDEN; i += G1_BLK) Ws[i] = W1[i];

    int base = blockIdx.x * G1_BLK;
    int node = base + threadIdx.x;

    unsigned long long acc2[8];
    #pragma unroll
    for (int q = 0; q < 8; q++) acc2[q] = 0ULL;

    // per-thread staging: 4 float4s per chunk; q = tid + i*G1_BLK; row=q>>2, c4=q&3
    float4 r[4];
    #pragma unroll
    for (int i = 0; i < 4; i++) {
        int q = threadIdx.x + i * G1_BLK;
        int row = q >> 2, c4 = q & 3;
        int nn = base + row;
        r[i] = (nn < n) ? *(const float4*)(x + (size_t)nn * F_IN + 0 + c4 * 4)
                        : make_float4(0.f, 0.f, 0.f, 0.f);
    }

    int p = 0;
    for (int ch = 0; ch < G1_NCH; ch++) {
        // stage regs -> smem buffer p (scalar STS to keep bank-conflict-free pad)
        #pragma unroll
        for (int i = 0; i < 4; i++) {
            int q = threadIdx.x + i * G1_BLK;
            int row = q >> 2, c4 = q & 3;
            xs[p][row][c4 * 4 + 0] = r[i].x;
            xs[p][row][c4 * 4 + 1] = r[i].y;
            xs[p][row][c4 * 4 + 2] = r[i].z;
            xs[p][row][c4 * 4 + 3] = r[i].w;
        }
        __syncthreads();
        if (ch + 1 < G1_NCH) {
            int kc = (ch + 1) * G1_KC;
            #pragma unroll
            for (int i = 0; i < 4; i++) {
                int q = threadIdx.x + i * G1_BLK;
                int row = q >> 2, c4 = q & 3;
                int nn = base + row;
                r[i] = (nn < n) ? *(const float4*)(x + (size_t)nn * F_IN + kc + c4 * 4)
                                : make_float4(0.f, 0.f, 0.f, 0.f);
            }
        }
        int kc = ch * G1_KC;
        #pragma unroll
        for (int c = 0; c < G1_KC; c++) {
            float xv = xs[p][threadIdx.x][c];
            unsigned long long xv2;
            asm("mov.b64 %0, {%1, %1};" : "=l"(xv2) : "f"(xv));
            const ulonglong2* w = (const ulonglong2*)&Ws[(kc + c) * HIDDEN];
            ulonglong2 wa = w[0];
            ulonglong2 wb = w[1];
            asm("fma.rn.f32x2 %0, %1, %2, %0;" : "+l"(acc2[0]) : "l"(xv2), "l"(wa.x));
            asm("fma.rn.f32x2 %0, %1, %2, %0;" : "+l"(acc2[1]) : "l"(xv2), "l"(wa.y));
            asm("fma.rn.f32x2 %0, %1, %2, %0;" : "+l"(acc2[2]) : "l"(xv2), "l"(wb.x));
            asm("fma.rn.f32x2 %0, %1, %2, %0;" : "+l"(acc2[3]) : "l"(xv2), "l"(wb.y));
            wa = w[2];
            wb = w[3];
            asm("fma.rn.f32x2 %0, %1, %2, %0;" : "+l"(acc2[4]) : "l"(xv2), "l"(wa.x));
            asm("fma.rn.f32x2 %0, %1, %2, %0;" : "+l"(acc2[5]) : "l"(xv2), "l"(wa.y));
            asm("fma.rn.f32x2 %0, %1, %2, %0;" : "+l"(acc2[6]) : "l"(xv2), "l"(wb.x));
            asm("fma.rn.f32x2 %0, %1, %2, %0;" : "+l"(acc2[7]) : "l"(xv2), "l"(wb.y));
        }
        p ^= 1;
    }
    if (node < n) {
        float4* h = (float4*)(g_h1s + (size_t)node * HIDDEN);
        #pragma unroll
        for (int q = 0; q < 4; q++) {
            float a, b, c, d;
            asm("mov.b64 {%0, %1}, %2;" : "=f"(a), "=f"(b) : "l"(acc2[2 * q]));
            asm("mov.b64 {%0, %1}, %2;" : "=f"(c), "=f"(d) : "l"(acc2[2 * q + 1]));
            h[q] = make_float4(a, b, c, d);
        }
    }
}

// ---------------- scale1: h1s *= dinv (join point) ----------------
__global__ void scale1_k(int n) {
    int i = blockIdx.x * blockDim.x + threadIdx.x;   // one float4 per thread
    if (i >= n * 4) return;
    float di = g_dinv[i >> 2];
    float4* p = (float4*)g_h1s + i;
    float4 v = *p;
    v.x *= di; v.y *= di; v.z *= di; v.w *= di;
    *p = v;
}

// ---------------- float4 warp gather over CSR (f32x2 adds) ----------------
__device__ __forceinline__ float4 csr_gather16(const float* __restrict__ tab,
                                               int row_stride, int start, int end,
                                               int lane) {
    int c4 = lane & 3;
    int g = lane >> 2;
    unsigned long long a0 = 0ULL, a1 = 0ULL;
    for (int chunk = start; chunk < end; chunk += 32) {
        int m = min(32, end - chunk);
        int srcs = (lane < m) ? g_csr[chunk + lane] : 0;
        #pragma unroll 4
        for (int k = 0; k < m; k += 8) {
            int j = k + g;
            int s = __shfl_sync(FULL, srcs, j & 31);
            if (j < m) {
                ulonglong2 t = *(const ulonglong2*)(tab + (size_t)s * row_stride + c4 * 4);
                asm("add.rn.f32x2 %0, %0, %1;" : "+l"(a0) : "l"(t.x));
                asm("add.rn.f32x2 %0, %0, %1;" : "+l"(a1) : "l"(t.y));
            }
        }
    }
    float4 acc;
    asm("mov.b64 {%0, %1}, %2;" : "=f"(acc.x), "=f"(acc.y) : "l"(a0));
    asm("mov.b64 {%0, %1}, %2;" : "=f"(acc.z), "=f"(acc.w) : "l"(a1));
    #pragma unroll
    for (int d = 4; d < 32; d <<= 1) {
        acc.x += __shfl_xor_sync(FULL, acc.x, d);
        acc.y += __shfl_xor_sync(FULL, acc.y, d);
        acc.z += __shfl_xor_sync(FULL, acc.z, d);
        acc.w += __shfl_xor_sync(FULL, acc.w, d);
    }
    return acc;
}

__device__ __forceinline__ float pick(float4 v, int comp) {
    float r = v.x;
    if (comp == 1) r = v.y;
    if (comp == 2) r = v.z;
    if (comp == 3) r = v.w;
    return r;
}

#define LANE_OF(j) (((j) >> 2) + 4 * ((j) & 3))

// ---------------- agg1 fused: gather + self, *dinv, +b1, relu, @W2, *dinv -> h2s ----
#define AGG_BLK 256
__global__ __launch_bounds__(AGG_BLK) void agg1_k(const float* __restrict__ b1,
                                                  const float* __restrict__ W2, int n) {
    __shared__ float W2s[HIDDEN * NCLS];
    __shared__ float b1s[HIDDEN];
    if (threadIdx.x < HIDDEN * NCLS) W2s[threadIdx.x] = W2[threadIdx.x];
    if (threadIdx.x < HIDDEN) b1s[threadIdx.x] = b1[threadIdx.x];
    __syncthreads();

    int wid = threadIdx.x >> 5, lane = threadIdx.x & 31;
    int v = blockIdx.x * (AGG_BLK / 32) + wid;
    if (v >= n) return;

    float4 acc4 = csr_gather16(g_h1s, HIDDEN, g_off[v], g_off[v + 1], lane);

    int f = (4 * (lane & 3) + ((lane >> 2) & 3)) & 15;
    float acc = pick(acc4, (lane >> 2) & 3);
    float di = g_dinv[v];
    acc += g_h1s[(size_t)v * HIDDEN + f];                // self loop (prescaled)
    float hr = fmaxf(fmaf(acc, di, b1s[f]), 0.0f);       // valid on lanes 0..15

    int c = (lane < NCLS) ? lane : 0;
    float o = 0.f;
    #pragma unroll
    for (int j = 0; j < HIDDEN; j++) {
        float hj = __shfl_sync(FULL, hr, LANE_OF(j));
        o = fmaf(hj, W2s[j * NCLS + c], o);
    }
    if (lane < HIDDEN)
        g_h2s[(size_t)v * H2_PAD + lane] = (lane < NCLS) ? o * di : 0.0f;
}

// ---------------- agg2: gather + self, *dinv, +b2 -> out ----------------
__global__ __launch_bounds__(AGG_BLK) void agg2_k(const float* __restrict__ b2,
                                                  float* __restrict__ out, int n) {
    int wid = threadIdx.x >> 5, lane = threadIdx.x & 31;
    int v = blockIdx.x * (AGG_BLK / 32) + wid;
    if (v >= n) return;

    float4 acc4 = csr_gather16(g_h2s, H2_PAD, g_off[v], g_off[v + 1], lane);

    int f = (4 * (lane & 3) + ((lane >> 2) & 3)) & 15;
    float acc = pick(acc4, (lane >> 2) & 3);
    if (lane < 16 && f < NCLS) {
        float total = acc + g_h2s[(size_t)v * H2_PAD + f];
        out[(size_t)v * NCLS + f] = fmaf(total, g_dinv[v], b2[f]);
    }
}

// ---------------- launch (fork/join: gemm1 overlaps CSR build) ----------------
extern "C" void kernel_launch(void* const* d_in, const int* in_sizes, int n_in,
                              void* d_out, int out_size) {
    const float* x  = (const float*)d_in[0];
    const void*  ei = d_in[1];
    const float* W1 = (const float*)d_in[2];
    const float* b1 = (const float*)d_in[3];
    const float* W2 = (const float*)d_in[4];
    const float* b2 = (const float*)d_in[5];
    float* out = (float*)d_out;

    int n = in_sizes[0] / F_IN;                 // 100000
    long long E = (long long)in_sizes[1] / 2;   // 3200000

    static cudaStream_t s2 = nullptr;
    static cudaEvent_t evA = nullptr, evB = nullptr;
    static void* degi_ptr = nullptr;
    if (s2 == nullptr) {   // one-time (outside capture); no allocation
        cudaStreamCreateWithFlags(&s2, cudaStreamNonBlocking);
        cudaEventCreateWithFlags(&evA, cudaEventDisableTiming);
        cudaEventCreateWithFlags(&evB, cudaEventDisableTiming);
        cudaGetSymbolAddress(&degi_ptr, g_degi);
    }

    int nb_e2 = (int)((E / 2 + 255) / 256);
    int nb_g1 = (n + G1_BLK - 1) / G1_BLK;
    int nb_sc = (n + SB - 1) / SB;
    int nb_ag = (n + (AGG_BLK / 32) - 1) / (AGG_BLK / 32);
    int nb_s1 = (n * 4 + 255) / 256;

    // fork: gemm1 (x, W1 only) on s2, concurrent with CSR build on default
    cudaEventRecord(evA, 0);
    cudaStreamWaitEvent(s2, evA, 0);
    gemm1_k<<<nb_g1, G1_BLK, 0, s2>>>(x, W1, n);
    cudaEventRecord(evB, s2);

    cudaMemsetAsync(degi_ptr, 0, (size_t)n * sizeof(int), 0);
    deg_k<<<nb_e2, 256>>>(ei, E);
    blocksum_k<<<nb_sc, SB>>>(n);
    bscan_k<<<1, 512>>>(nb_sc);
    fill_k<<<nb_sc, SB>>>(n, (int)E);
    csr_k<<<nb_e2, 256>>>(ei, E);

    // join, then dependent tail
    cudaStreamWaitEvent(0, evB, 0);
    scale1_k<<<nb_s1, 256>>>(n);
    agg1_k<<<nb_ag, AGG_BLK>>>(b1, W2, n);
    agg2_k<<<nb_ag, AGG_BLK>>>(b2, out, n);
}